// round 2
// baseline (speedup 1.0000x reference)
#include <cuda_runtime.h>

// Shapes
// x:  [64, 3, 224, 224]
// h1: [64, 64, 112, 112]   (scratch, reused per expert)
// conv2 out pooled -> gap[expert][64][128] (sums over 56*56)
// logits [64,2], mask[64], out: 128 floats + freq at out[128]

#define NB 64

__device__ float g_h1[NB * 64 * 112 * 112];   // ~205 MB scratch
__device__ float g_gap[2 * NB * 128];         // pooled sums per expert
__device__ float g_tlog[NB * 2];
__device__ int   g_mask[NB];

__global__ void zero_gap_kernel() {
    int i = blockIdx.x * blockDim.x + threadIdx.x;
    if (i < 2 * NB * 128) g_gap[i] = 0.f;
}

// ---------------------------------------------------------------------------
// conv1: 3 -> 64, 3x3, stride 2, SAME (pad_lo=0, pad_hi=1), 224 -> 112, +ReLU
// grid: (49 tiles, 64 images), block 256. Output tile 16x16.
// ---------------------------------------------------------------------------
__global__ void __launch_bounds__(256) conv1_kernel(
    const float* __restrict__ x,
    const float* __restrict__ w,      // [64][3][3][3]
    const float* __restrict__ bias)   // [64]
{
    __shared__ float sIn[3 * 33 * 33];
    __shared__ __align__(16) float sW[64 * 28];  // padded 27 -> 28 for float4
    __shared__ float sB[64];

    int b = blockIdx.y;
    int tile = blockIdx.x;
    int ty = tile / 7, tx = tile % 7;
    int tid = threadIdx.x;
    int y0 = ty * 32, x0 = tx * 32;

    for (int i = tid; i < 3 * 33 * 33; i += 256) {
        int c = i / 1089, rem = i % 1089;
        int iy = rem / 33, ix = rem % 33;
        int gy = y0 + iy, gx = x0 + ix;
        float v = 0.f;
        if (gy < 224 && gx < 224)
            v = x[((b * 3 + c) * 224 + gy) * 224 + gx];
        sIn[i] = v;
    }
    for (int i = tid; i < 64 * 27; i += 256) {
        int oc = i / 27, k = i % 27;
        sW[oc * 28 + k] = w[i];
    }
    if (tid < 64) sB[tid] = bias[tid];
    __syncthreads();

    int ly = tid / 16, lx = tid % 16;
    float rin[27];
    #pragma unroll
    for (int c = 0; c < 3; c++)
        #pragma unroll
        for (int r = 0; r < 3; r++)
            #pragma unroll
            for (int s = 0; s < 3; s++)
                rin[c * 9 + r * 3 + s] = sIn[c * 1089 + (2 * ly + r) * 33 + (2 * lx + s)];

    int oy = ty * 16 + ly, ox = tx * 16 + lx;
    float* outp = &g_h1[(size_t)b * 64 * 112 * 112 + oy * 112 + ox];

    for (int oc = 0; oc < 64; oc++) {
        float4 wv4[7];
        const float4* wp4 = (const float4*)(sW + oc * 28);
        #pragma unroll
        for (int t = 0; t < 7; t++) wv4[t] = wp4[t];
        const float* wv = (const float*)wv4;
        float acc = sB[oc];
        #pragma unroll
        for (int k = 0; k < 27; k++) acc = fmaf(rin[k], wv[k], acc);
        outp[oc * (112 * 112)] = fmaxf(acc, 0.f);
    }
}

// ---------------------------------------------------------------------------
// conv2: 64 -> 128, 3x3, stride 2, SAME, 112 -> 56, +bias +ReLU, fused GAP.
// grid: (49 tiles, 2 oc-blocks, 64 images), block 128.
// Tile: 64 oc x 8x8 px. Thread: 8 oc x (2x2) px = 32 accumulators.
// ---------------------------------------------------------------------------
__global__ void __launch_bounds__(128) conv2_kernel(
    const float* __restrict__ w,      // [128][64][3][3]
    const float* __restrict__ bias,   // [128]
    int expert)
{
    __shared__ __align__(16) float sIn[4][17][18];
    __shared__ __align__(16) float sW[36][64];

    int b   = blockIdx.z;
    int ocb = blockIdx.y;      // 0 or 1
    int tile = blockIdx.x;
    int ty = tile / 7, tx = tile % 7;
    int tid = threadIdx.x;

    int g_oc = tid >> 4;       // 0..7   (8 ocs each)
    int g_px = tid & 15;       // 0..15  (2x2 px each)
    int gy2 = g_px >> 2, gx2 = g_px & 3;
    int y0 = ty * 16, x0 = tx * 16;    // input tile origin

    float acc[8][4];
    #pragma unroll
    for (int j = 0; j < 8; j++)
        #pragma unroll
        for (int p = 0; p < 4; p++) acc[j][p] = 0.f;

    const float* h1base = g_h1 + (size_t)b * 64 * 112 * 112;

    for (int cc = 0; cc < 64; cc += 4) {
        __syncthreads();
        // input chunk: 4 channels x 17x17
        for (int i = tid; i < 4 * 17 * 17; i += 128) {
            int cl = i / 289, rem = i % 289;
            int iy = rem / 17, ix = rem % 17;
            int gy = y0 + iy, gx = x0 + ix;
            float v = 0.f;
            if (gy < 112 && gx < 112)
                v = h1base[(cc + cl) * (112 * 112) + gy * 112 + gx];
            sIn[cl][iy][ix] = v;
        }
        // weight chunk: 64 oc x 36 (4c x 9 taps), coalesced over k
        for (int i = tid; i < 64 * 36; i += 128) {
            int o = i / 36, k = i % 36;
            sW[k][o] = w[(ocb * 64 + o) * 576 + cc * 9 + k];
        }
        __syncthreads();

        int ry0 = gy2 * 4, cx0 = gx2 * 4;
        #pragma unroll
        for (int cl = 0; cl < 4; cl++)
            #pragma unroll
            for (int r = 0; r < 3; r++)
                #pragma unroll
                for (int s = 0; s < 3; s++) {
                    int k = cl * 9 + r * 3 + s;
                    float4 wa = *(const float4*)&sW[k][g_oc * 8];
                    float4 wb = *(const float4*)&sW[k][g_oc * 8 + 4];
                    float iv0 = sIn[cl][ry0 + r][cx0 + s];
                    float iv1 = sIn[cl][ry0 + r][cx0 + s + 2];
                    float iv2 = sIn[cl][ry0 + r + 2][cx0 + s];
                    float iv3 = sIn[cl][ry0 + r + 2][cx0 + s + 2];
                    float wv[8] = {wa.x, wa.y, wa.z, wa.w, wb.x, wb.y, wb.z, wb.w};
                    float iv[4] = {iv0, iv1, iv2, iv3};
                    #pragma unroll
                    for (int j = 0; j < 8; j++)
                        #pragma unroll
                        for (int p = 0; p < 4; p++)
                            acc[j][p] = fmaf(wv[j], iv[p], acc[j][p]);
                }
    }

    // bias + relu + partial GAP (reduce over this block's 64 px)
    float* gap = &g_gap[expert * (NB * 128)];
    #pragma unroll
    for (int j = 0; j < 8; j++) {
        int oc = ocb * 64 + g_oc * 8 + j;
        float bv = __ldg(&bias[oc]);
        float s = 0.f;
        #pragma unroll
        for (int p = 0; p < 4; p++) s += fmaxf(acc[j][p] + bv, 0.f);
        #pragma unroll
        for (int off = 8; off >= 1; off >>= 1)
            s += __shfl_down_sync(0xffffffffu, s, off, 16);
        if ((tid & 15) == 0) atomicAdd(&gap[b * 128 + oc], s);
    }
}

// ---------------------------------------------------------------------------
// texture-expert logits + gate mask.  conf<=0.9  <=>  |l0-l1| <= ln(9)
// ---------------------------------------------------------------------------
__global__ void logits_t_kernel(const float* __restrict__ wf,
                                const float* __restrict__ bf)
{
    int b = threadIdx.x;
    if (b >= NB) return;
    float l0 = bf[0], l1 = bf[1];
    const float inv = 1.0f / 3136.0f;
    for (int k = 0; k < 128; k++) {
        float g = g_gap[b * 128 + k] * inv;
        l0 = fmaf(g, wf[2 * k], l0);
        l1 = fmaf(g, wf[2 * k + 1], l1);
    }
    g_tlog[2 * b] = l0;
    g_tlog[2 * b + 1] = l1;
    g_mask[b] = (fabsf(l0 - l1) <= 2.1972245773362196f) ? 1 : 0;
}

__global__ void final_kernel(const float* __restrict__ wf,
                             const float* __restrict__ bf,
                             float* __restrict__ out)
{
    __shared__ int cnt[NB];
    int b = threadIdx.x;
    if (b < NB) {
        float l0 = bf[0], l1 = bf[1];
        const float inv = 1.0f / 3136.0f;
        for (int k = 0; k < 128; k++) {
            float g = g_gap[NB * 128 + b * 128 + k] * inv;
            l0 = fmaf(g, wf[2 * k], l0);
            l1 = fmaf(g, wf[2 * k + 1], l1);
        }
        int m = g_mask[b];
        float t0 = g_tlog[2 * b], t1 = g_tlog[2 * b + 1];
        out[2 * b]     = m ? (0.7f * t0 + 0.3f * l0) : t0;
        out[2 * b + 1] = m ? (0.7f * t1 + 0.3f * l1) : t1;
        cnt[b] = m;
    }
    __syncthreads();
    if (b == 0) {
        int c = 0;
        for (int i = 0; i < NB; i++) c += cnt[i];
        out[128] = (float)c / (float)NB;
    }
}

extern "C" void kernel_launch(void* const* d_in, const int* in_sizes, int n_in,
                              void* d_out, int out_size)
{
    const float* x    = (const float*)d_in[0];
    const float* t_w1 = (const float*)d_in[1];
    const float* t_b1 = (const float*)d_in[2];
    const float* t_w2 = (const float*)d_in[3];
    const float* t_b2 = (const float*)d_in[4];
    const float* t_wf = (const float*)d_in[5];
    const float* t_bf = (const float*)d_in[6];
    const float* f_w1 = (const float*)d_in[7];
    const float* f_b1 = (const float*)d_in[8];
    const float* f_w2 = (const float*)d_in[9];
    const float* f_b2 = (const float*)d_in[10];
    const float* f_wf = (const float*)d_in[11];
    const float* f_bf = (const float*)d_in[12];
    float* out = (float*)d_out;

    zero_gap_kernel<<<32, 512>>>();

    // texture expert
    conv1_kernel<<<dim3(49, 64), 256>>>(x, t_w1, t_b1);
    conv2_kernel<<<dim3(49, 2, 64), 128>>>(t_w2, t_b2, 0);
    logits_t_kernel<<<1, 64>>>(t_wf, t_bf);

    // frequency expert (reuses h1 scratch; same stream serializes)
    conv1_kernel<<<dim3(49, 64), 256>>>(x, f_w1, f_b1);
    conv2_kernel<<<dim3(49, 2, 64), 128>>>(f_w2, f_b2, 1);
    final_kernel<<<1, 64>>>(f_wf, f_bf, out);
}